// round 14
// baseline (speedup 1.0000x reference)
#include <cuda_runtime.h>
#include <cuda.h>
#include <cstdint>
#include <math.h>

// ============================ problem constants ============================
#define L_DIM  1024
#define B_DIM  8
#define CIN    1024
#define COUT   1024
#define KEXP   4
#define CCOND  256
#define HIDD   64

// ============================ GEMM tiling ============================
#define TM   128            // M tile (L dimension)
#define TN   128            // N tile (C_OUT dimension)
#define KC   32             // K floats per stage (128B row = SW128 atom)
#define NKC  (CIN / KC)     // 32 K-chunks
#define NS   3              // pipeline stages
#define NWARP_C 4           // compute warps (64x64 warp tile, 2x2)
#define NTHREADS (NWARP_C * 32 + 32)   // + 1 producer warp = 160
#define NTILES ((L_DIM / TM) * (COUT / TN) * B_DIM)   // 512

#define A_STAGE_BYTES (TM * KC * 4)          // 16384
#define B_STAGE_BYTES (TN * KC * 4)          // 16384
#define STAGE_BYTES   (A_STAGE_BYTES + B_STAGE_BYTES)

#define OFF_FULL   0u
#define OFF_EMPTY  (8u * NS)
#define OFF_IDX    (8u * NS * 2u)                              // tile-index broadcast slot
#define OFF_A      1024u
#define OFF_B      (1024u + NS * A_STAGE_BYTES)                // 50176 (1024-aligned)
#define SMEM_TOTAL ((int)(OFF_B + NS * B_STAGE_BYTES))         // 99328 -> 2 CTAs/SM

// ============================ scratch (device globals; no allocs) ============================
__device__ __align__(256) float g_w[(size_t)B_DIM * COUT * CIN];   // 32 MB aggregated + tf32-RNA weights
__device__ __align__(16)  float g_bb[B_DIM * COUT];                // aggregated bias
__device__ __align__(16)  float g_att[B_DIM * KEXP];               // softmax attention
__device__ __align__(16)  float g_h[B_DIM * HIDD];                 // fc1 hidden activations
__device__ unsigned int   g_tile_ctr;                              // persistent-GEMM work counter

// ============================ PTX helpers (sm_100 BASELINE only) ============================
__device__ __forceinline__ uint32_t smem_u32(const void* p) {
    uint32_t a;
    asm("{ .reg .u64 t; cvta.to.shared.u64 t, %1; cvt.u32.u64 %0, t; }" : "=r"(a) : "l"(p));
    return a;
}

#define MBARRIER_INIT(addr, cnt) \
    asm volatile("mbarrier.init.shared.b64 [%0], %1;" :: "r"(addr), "r"((uint32_t)(cnt)) : "memory")

#define MBARRIER_EXPECT_TX(addr, bytes) \
    asm volatile("mbarrier.arrive.expect_tx.shared.b64 _, [%0], %1;" :: "r"(addr), "r"((uint32_t)(bytes)) : "memory")

#define MBARRIER_ARRIVE(addr) \
    asm volatile("mbarrier.arrive.shared.b64 _, [%0];" :: "r"(addr) : "memory")

#define MBAR_INVAL(addr) \
    asm volatile("mbarrier.inval.shared.b64 [%0];" :: "r"(addr) : "memory")

#define MBARRIER_WAIT_PARITY(mbar_smem_addr, phase_parity) do {                          \
    uint32_t _mbar = (uint32_t)(mbar_smem_addr);                                         \
    uint32_t _parity = (uint32_t)(phase_parity);                                         \
    uint32_t _done;                                                                      \
    asm volatile(                                                                        \
        "{\n\t"                                                                          \
        ".reg .pred p;\n\t"                                                              \
        "mbarrier.try_wait.parity.acquire.cta.shared::cta.b64 p, [%1], %2;\n\t"          \
        "selp.b32 %0, 1, 0, p;\n\t"                                                      \
        "}"                                                                              \
        : "=r"(_done) : "r"(_mbar), "r"(_parity) : "memory");                            \
    if (!_done) {                                                                        \
        asm volatile(                                                                    \
            "{\n\t"                                                                      \
            ".reg .pred P1;\n\t"                                                         \
            "WAIT_LOOP_%=:\n\t"                                                          \
            "mbarrier.try_wait.parity.acquire.cta.shared::cta.b64 P1, [%0], %1, 0x989680;\n\t" \
            "@P1 bra.uni WAIT_DONE_%=;\n\t"                                              \
            "bra.uni WAIT_LOOP_%=;\n\t"                                                  \
            "WAIT_DONE_%=:\n\t"                                                          \
            "}"                                                                          \
            :: "r"(_mbar), "r"(_parity) : "memory");                                     \
    }                                                                                    \
} while (0)

#define TMA_LOAD_3D(smem_addr, tensor_map, cx, cy, cz, mbar) \
    asm volatile( \
        "cp.async.bulk.tensor.3d.shared::cta.global.tile.mbarrier::complete_tx::bytes " \
        "[%0], [%1, {%2, %3, %4}], [%5];" \
        :: "r"((uint32_t)(smem_addr)), "l"(tensor_map), \
           "r"((int32_t)(cx)), "r"((int32_t)(cy)), "r"((int32_t)(cz)), \
           "r"((uint32_t)(mbar)) \
        : "memory")

#define FENCE_PROXY() \
    asm volatile("fence.proxy.async.shared::cta;" ::: "memory")

// ldmatrix x4: four 8x8 b16 matrices; per-lane row address in [addr].
#define LDSM_X4(r, addr) \
    asm volatile("ldmatrix.sync.aligned.m8n8.x4.shared.b16 {%0,%1,%2,%3}, [%4];" \
        : "=r"((r)[0]), "=r"((r)[1]), "=r"((r)[2]), "=r"((r)[3]) : "r"(addr))

// tf32 round-to-nearest (ties away): add half-ulp at bit 13, mask. Carry into
// the exponent is correct rounding. Inputs are finite, so no NaN/Inf handling.
__device__ __forceinline__ uint32_t tf32_rna_u32(uint32_t u) {
    return (u + 0x1000u) & 0xFFFFE000u;
}
__device__ __forceinline__ float tf32_round(float v) {
    return __uint_as_float(tf32_rna_u32(__float_as_uint(v)));
}

// mma.sync m16n8k8 tf32 (sm_80+ baseline)
__device__ __forceinline__ void mma_tf32(float* d, const uint32_t* a, const uint32_t* b) {
    asm volatile(
        "mma.sync.aligned.m16n8k8.row.col.f32.tf32.tf32.f32 "
        "{%0,%1,%2,%3}, {%4,%5,%6,%7}, {%8,%9}, {%0,%1,%2,%3};"
        : "+f"(d[0]), "+f"(d[1]), "+f"(d[2]), "+f"(d[3])
        : "r"(a[0]), "r"(a[1]), "r"(a[2]), "r"(a[3]), "r"(b[0]), "r"(b[1]));
}

// ============================ kernel 1a: fc1 hidden (multi-SM, warp-cooperative) ============================
__global__ void attn_h_kernel(const float* __restrict__ cond,
                              const float* __restrict__ fc1w,
                              const float* __restrict__ fc1b) {
    const int w = threadIdx.x >> 5, l = threadIdx.x & 31;
    #pragma unroll
    for (int r = 0; r < 4; r++) {
        const int idx = blockIdx.x * 32 + w * 4 + r;   // 0..511
        const int b = idx >> 6, j = idx & 63;
        const float* c = cond + b * CCOND;
        const float* fw = fc1w + j * CCOND;
        float s = 0.0f;
        #pragma unroll
        for (int i = 0; i < CCOND / 32; i++)           // 8 coalesced loads, MLP 8
            s = fmaf(c[l + 32 * i], fw[l + 32 * i], s);
        #pragma unroll
        for (int o = 16; o; o >>= 1) s += __shfl_xor_sync(0xFFFFFFFFu, s, o);
        if (l == 0) g_h[idx] = fmaxf(s + fc1b[j], 0.0f);
    }
}

// ============================ kernel 1b: logits + softmax + aggregated bias ============================
__global__ void attn_rest_kernel(const float* __restrict__ fc2w, const float* __restrict__ fc2b,
                                 const float* __restrict__ bias) {
    __shared__ float h[B_DIM * HIDD];
    __shared__ float lo[B_DIM][KEXP];
    __shared__ float att[B_DIM][KEXP];
    const int t = threadIdx.x;   // 512 threads

    if (t < B_DIM * HIDD) h[t] = g_h[t];
    __syncthreads();

    if (t < B_DIM * KEXP) {
        const int b = t >> 2, k = t & 3;
        const float* wv = fc2w + k * HIDD;
        float acc = fc2b[k];
        #pragma unroll 8
        for (int i = 0; i < HIDD; i++) acc = fmaf(h[b * HIDD + i], wv[i], acc);
        lo[b][k] = acc * (1.0f / 30.0f);
    }
    __syncthreads();

    if (t < B_DIM) {
        float m = fmaxf(fmaxf(lo[t][0], lo[t][1]), fmaxf(lo[t][2], lo[t][3]));
        float e[KEXP], s = 0.0f;
        #pragma unroll
        for (int k = 0; k < KEXP; k++) { e[k] = expf(lo[t][k] - m); s += e[k]; }
        float inv = 1.0f / s;
        #pragma unroll
        for (int k = 0; k < KEXP; k++) { att[t][k] = e[k] * inv; g_att[t * KEXP + k] = e[k] * inv; }
    }
    __syncthreads();

    for (int idx = t; idx < B_DIM * COUT; idx += 512) {
        const int b = idx >> 10, o = idx & 1023;
        float acc = 0.0f;
        #pragma unroll
        for (int k = 0; k < KEXP; k++) acc = fmaf(att[b][k], bias[k * COUT + o], acc);
        g_bb[idx] = acc;
    }
}

// ============================ kernel 2: per-sample weight aggregation (+ tf32-RNA round) ============================
__global__ void wagg_kernel(const float* __restrict__ weight) {
    // reset the persistent-GEMM work counter (stream-ordered before the GEMM launch)
    if (blockIdx.x == 0 && threadIdx.x == 0) g_tile_ctr = 0u;

    __shared__ float a[B_DIM * KEXP];
    if (threadIdx.x < B_DIM * KEXP) a[threadIdx.x] = g_att[threadIdx.x];
    __syncthreads();

    const int t = blockIdx.x * blockDim.x + threadIdx.x;   // over COUT*CIN/4 float4s
    const float4* w4 = reinterpret_cast<const float4*>(weight);
    float4 wk[KEXP];
    #pragma unroll
    for (int k = 0; k < KEXP; k++) wk[k] = w4[k * (COUT * CIN / 4) + t];

    float4* g4 = reinterpret_cast<float4*>(g_w);
    #pragma unroll
    for (int b = 0; b < B_DIM; b++) {
        float4 acc = make_float4(0.f, 0.f, 0.f, 0.f);
        #pragma unroll
        for (int k = 0; k < KEXP; k++) {
            const float ab = a[b * KEXP + k];
            acc.x = fmaf(ab, wk[k].x, acc.x);
            acc.y = fmaf(ab, wk[k].y, acc.y);
            acc.z = fmaf(ab, wk[k].z, acc.z);
            acc.w = fmaf(ab, wk[k].w, acc.w);
        }
        acc.x = tf32_round(acc.x); acc.y = tf32_round(acc.y);
        acc.z = tf32_round(acc.z); acc.w = tf32_round(acc.w);
        g4[b * (COUT * CIN / 4) + t] = acc;
    }
}

// ============================ kernel 3: persistent tf32 mma.sync GEMM (dynamic tile stealing) ============================
// CTA tile 128x128, 2 persistent CTAs/SM grab tiles from g_tile_ctr.
// Tile order groups by batch b (64 tiles/b): concurrent window's operands stay L2-resident.
__global__ void __launch_bounds__(NTHREADS, 2)
gemm_tf32_kernel(const __grid_constant__ CUtensorMap tmx,
                 const __grid_constant__ CUtensorMap tmw,
                 const float* __restrict__ bb,
                 float* __restrict__ out,
                 int enabled) {
    if (!enabled) return;     // fallback path active: SIMT kernel does the work
    extern __shared__ char smem[];
    const uint32_t sb = smem_u32(smem);
    const int tid  = threadIdx.x;
    const int wid  = tid >> 5;
    const int lane = tid & 31;
    const int g = lane >> 2;      // group id (0..7)
    const int t = lane & 3;       // thread-in-group (0..3)

    if (tid == 0) {
        #pragma unroll
        for (int s = 0; s < NS; s++) {
            MBARRIER_INIT(sb + OFF_FULL + 8 * s, 1);        // tx-based
            MBARRIER_INIT(sb + OFF_EMPTY + 8 * s, NWARP_C); // 1 arrive per compute warp
        }
        FENCE_PROXY();
    }
    __syncthreads();

    // ---- per-lane constants (computed once, reused across tiles) ----
    const int wm = wid & 1;        // 0..1 -> M offset (64 rows)
    const int wn = wid >> 1;       // 0..1 -> N offset (64 cols)
    const int srot = wid & 3;
    const int r8   = lane & 7;
    const int subA = (lane >> 3) & 1;
    const int tadd = lane >> 4;
    const int hA   = lane >> 4;
    const int hB   = (lane >> 3) & 1;
    const uint32_t uxor = (uint32_t)(r8 >> 1);
    const uint32_t vA = (uint32_t)((hA ^ (r8 & 1)) << 4);
    const uint32_t vB = (uint32_t)((hB ^ (r8 & 1)) << 4);

    uint32_t rowA[4], rowB[4];
    #pragma unroll
    for (int i = 0; i < 4; i++)
        rowA[i] = (uint32_t)(wm * 64 + i * 16 + subA * 8 + r8) * 128u;
    #pragma unroll
    for (int p = 0; p < 4; p++)
        rowB[p] = (uint32_t)(wn * 64 + (p * 2 + tadd) * 8 + r8) * 128u;

    // pipeline cursors persist across tiles (both sides advance NKC stages/tile)
    int ps = 0, pp = 1;   // producer cursor on empty[]
    int cs = 0, cp = 0;   // consumer cursor on full[]

    volatile uint32_t* idx_smem = reinterpret_cast<volatile uint32_t*>(smem + OFF_IDX);

    for (;;) {
        __syncthreads();
        if (tid == 0) *idx_smem = atomicAdd(&g_tile_ctr, 1u);
        __syncthreads();
        const uint32_t idx = *idx_smem;
        if (idx >= NTILES) break;

        // tile order: b = idx>>6 (outer), then o0, l0 -- keeps concurrent set in one/two b's
        const int l0 = (int)(idx & 7) * TM;
        const int o0 = (int)((idx >> 3) & 7) * TN;
        const int b  = (int)(idx >> 6);

        if (wid == NWARP_C) {
            // ---------------- producer warp ----------------
            if (lane == 0) {
                #pragma unroll 1
                for (int kc = 0; kc < NKC; kc++) {
                    MBARRIER_WAIT_PARITY(sb + OFF_EMPTY + 8 * ps, pp);
                    MBARRIER_EXPECT_TX(sb + OFF_FULL + 8 * ps, STAGE_BYTES);
                    TMA_LOAD_3D(sb + OFF_A + ps * A_STAGE_BYTES, &tmx, kc * KC, b, l0, sb + OFF_FULL + 8 * ps);
                    TMA_LOAD_3D(sb + OFF_B + ps * B_STAGE_BYTES, &tmw, kc * KC, o0, b, sb + OFF_FULL + 8 * ps);
                    if (++ps == NS) { ps = 0; pp ^= 1; }
                }
            }
        } else {
            // ---------------- compute warps (64x64 each) ----------------
            float acc[4][8][4];
            #pragma unroll
            for (int i = 0; i < 4; i++)
                #pragma unroll
                for (int j = 0; j < 8; j++)
                    #pragma unroll
                    for (int q = 0; q < 4; q++) acc[i][j][q] = 0.0f;

            #pragma unroll 1
            for (int kc = 0; kc < NKC; kc++) {
                MBARRIER_WAIT_PARITY(sb + OFF_FULL + 8 * cs, cp);
                const uint32_t sA = sb + OFF_A + cs * A_STAGE_BYTES;
                const uint32_t sB = sb + OFF_B + cs * B_STAGE_BYTES;

                #pragma unroll
                for (int si = 0; si < 4; si++) {
                    const int s = (si + srot) & 3;
                    const uint32_t offA = ((((uint32_t)s ^ uxor) & 3u) << 5) | vA;
                    const uint32_t offB = ((((uint32_t)s ^ uxor) & 3u) << 5) | vB;

                    uint32_t a[4][4];
                    uint32_t bfr[4][4];
                    LDSM_X4(a[0], sA + rowA[0] + offA);
                    LDSM_X4(a[1], sA + rowA[1] + offA);
                    LDSM_X4(a[2], sA + rowA[2] + offA);
                    LDSM_X4(a[3], sA + rowA[3] + offA);
                    LDSM_X4(bfr[0], sB + rowB[0] + offB);
                    LDSM_X4(bfr[1], sB + rowB[1] + offB);
                    LDSM_X4(bfr[2], sB + rowB[2] + offB);
                    LDSM_X4(bfr[3], sB + rowB[3] + offB);

                    #pragma unroll
                    for (int i = 0; i < 4; i++)
                        #pragma unroll
                        for (int q = 0; q < 4; q++) a[i][q] = tf32_rna_u32(a[i][q]);

                    #pragma unroll
                    for (int p = 0; p < 4; p++) {
                        #pragma unroll
                        for (int i = 0; i < 4; i++) {
                            mma_tf32(acc[i][2 * p],     a[i], bfr[p]);
                            mma_tf32(acc[i][2 * p + 1], a[i], bfr[p] + 2);
                        }
                    }
                }

                if (lane == 0) MBARRIER_ARRIVE(sb + OFF_EMPTY + 8 * cs);
                if (++cs == NS) { cs = 0; cp ^= 1; }
            }

            // ---------------- epilogue: registers -> gmem with bias ----------------
            const int colbase = o0 + wn * 64 + 2 * t;
            float2 bv[8];
            #pragma unroll
            for (int j = 0; j < 8; j++)
                bv[j] = *reinterpret_cast<const float2*>(bb + b * COUT + colbase + j * 8);

            #pragma unroll
            for (int i = 0; i < 4; i++) {
                #pragma unroll
                for (int p = 0; p < 2; p++) {
                    const int l = l0 + wm * 64 + i * 16 + g + 8 * p;
                    float* orow = out + ((size_t)l * B_DIM + b) * COUT + colbase;
                    #pragma unroll
                    for (int j = 0; j < 8; j++) {
                        float2 v;
                        v.x = acc[i][j][2 * p]     + bv[j].x;
                        v.y = acc[i][j][2 * p + 1] + bv[j].y;
                        *reinterpret_cast<float2*>(orow + j * 8) = v;
                    }
                }
            }
        }
    }

    __syncthreads();
    if (tid == 0) {
        #pragma unroll
        for (int s = 0; s < NS; s++) {
            MBAR_INVAL(sb + OFF_FULL + 8 * s);
            MBAR_INVAL(sb + OFF_EMPTY + 8 * s);
        }
    }
}

// ============================ fallback: SIMT fp32 GEMM (no TMA/tensor maps) ============================
__global__ void __launch_bounds__(256, 2)
gemm_fallback_kernel(const float* __restrict__ x, const float* __restrict__ bb,
                     float* __restrict__ out, int enabled) {
    if (!enabled) return;
    __shared__ float sx[64][33];     // 64 rows x 32 k (padded)
    const int l0 = blockIdx.x * 64;
    const int o0 = blockIdx.y * 128;
    const int b  = blockIdx.z;
    const int tid = threadIdx.x;
    const int tr = tid >> 5;         // 0..7 row group
    const int tc = tid & 31;

    float acc[8][4];
    #pragma unroll
    for (int i = 0; i < 8; i++)
        #pragma unroll
        for (int j = 0; j < 4; j++) acc[i][j] = 0.0f;

    for (int k0 = 0; k0 < CIN; k0 += 32) {
        __syncthreads();
        #pragma unroll
        for (int i = 0; i < 8; i++) {
            const int row = tr + i * 8;
            sx[row][tc] = x[((size_t)(l0 + row) * B_DIM + b) * CIN + k0 + tc];
        }
        __syncthreads();
        #pragma unroll 4
        for (int kk = 0; kk < 32; kk++) {
            float wv[4];
            #pragma unroll
            for (int j = 0; j < 4; j++)
                wv[j] = g_w[((size_t)b * COUT + o0 + tc + 32 * j) * CIN + k0 + kk];
            #pragma unroll
            for (int i = 0; i < 8; i++) {
                const float xv = sx[tr + i * 8][kk];
                #pragma unroll
                for (int j = 0; j < 4; j++) acc[i][j] = fmaf(xv, wv[j], acc[i][j]);
            }
        }
    }
    #pragma unroll
    for (int i = 0; i < 8; i++) {
        const int l = l0 + tr + i * 8;
        #pragma unroll
        for (int j = 0; j < 4; j++) {
            const int o = o0 + tc + 32 * j;
            out[((size_t)l * B_DIM + b) * COUT + o] = acc[i][j] + bb[b * COUT + o];
        }
    }
}

// ============================ host launch ============================
typedef CUresult (CUDAAPI *EncodeTiledFn)(
    CUtensorMap*, CUtensorMapDataType, cuuint32_t, void*,
    const cuuint64_t*, const cuuint64_t*, const cuuint32_t*, const cuuint32_t*,
    CUtensorMapInterleave, CUtensorMapSwizzle, CUtensorMapL2promotion, CUtensorMapFloatOOBfill);

extern "C" void kernel_launch(void* const* d_in, const int* in_sizes, int n_in,
                              void* d_out, int out_size) {
    const float* x      = (const float*)d_in[0];
    const float* cond   = (const float*)d_in[1];
    const float* fc1w   = (const float*)d_in[2];
    const float* fc1b   = (const float*)d_in[3];
    const float* fc2w   = (const float*)d_in[4];
    const float* fc2b   = (const float*)d_in[5];
    const float* weight = (const float*)d_in[6];
    const float* bias   = (const float*)d_in[7];
    float* out = (float*)d_out;

    void *p_w = nullptr, *p_bb = nullptr;
    cudaGetSymbolAddress(&p_w, g_w);
    cudaGetSymbolAddress(&p_bb, g_bb);

    // Resolve cuTensorMapEncodeTiled defensively; fall back to SIMT path on ANY failure.
    EncodeTiledFn enc = nullptr;
    {
        cudaDriverEntryPointQueryResult qres = cudaDriverEntryPointSymbolNotFound;
        cudaError_t e = cudaGetDriverEntryPointByVersion(
            "cuTensorMapEncodeTiled", (void**)&enc, 12000, cudaEnableDefault, &qres);
        if (e != cudaSuccess || qres != cudaDriverEntryPointSuccess) enc = nullptr;
        if (!enc) {
            qres = cudaDriverEntryPointSymbolNotFound;
            e = cudaGetDriverEntryPoint("cuTensorMapEncodeTiled", (void**)&enc,
                                        cudaEnableDefault, &qres);
            if (e != cudaSuccess || qres != cudaDriverEntryPointSuccess) enc = nullptr;
        }
    }

    CUtensorMap tmx, tmw;
    bool fast = (enc != nullptr);
    if (fast) {
        // x: logical dims (CIN, B, L), box (KC, 1, TM), SW128
        cuuint64_t dimsx[3]    = {CIN, B_DIM, L_DIM};
        cuuint64_t stridesx[2] = {(cuuint64_t)CIN * 4, (cuuint64_t)CIN * B_DIM * 4};
        cuuint32_t boxx[3]     = {KC, 1, TM};
        cuuint32_t es[3]       = {1, 1, 1};
        if (enc(&tmx, CU_TENSOR_MAP_DATA_TYPE_FLOAT32, 3, (void*)x, dimsx, stridesx, boxx, es,
                CU_TENSOR_MAP_INTERLEAVE_NONE, CU_TENSOR_MAP_SWIZZLE_128B,
                CU_TENSOR_MAP_L2_PROMOTION_L2_128B, CU_TENSOR_MAP_FLOAT_OOB_FILL_NONE)
            != CUDA_SUCCESS) fast = false;
        // w_agg: logical dims (CIN, COUT, B), box (KC, TN, 1), SW128
        cuuint64_t dimsw[3]    = {CIN, COUT, B_DIM};
        cuuint64_t stridesw[2] = {(cuuint64_t)CIN * 4, (cuuint64_t)CIN * COUT * 4};
        cuuint32_t boxw[3]     = {KC, TN, 1};
        if (fast &&
            enc(&tmw, CU_TENSOR_MAP_DATA_TYPE_FLOAT32, 3, p_w, dimsw, stridesw, boxw, es,
                CU_TENSOR_MAP_INTERLEAVE_NONE, CU_TENSOR_MAP_SWIZZLE_128B,
                CU_TENSOR_MAP_L2_PROMOTION_L2_128B, CU_TENSOR_MAP_FLOAT_OOB_FILL_NONE)
            != CUDA_SUCCESS) fast = false;
    }
    if (!fast) {
        memset(&tmx, 0, sizeof(tmx));
        memset(&tmw, 0, sizeof(tmw));
    }

    attn_h_kernel<<<16, 256>>>(cond, fc1w, fc1b);
    attn_rest_kernel<<<1, 512>>>(fc2w, fc2b, bias);
    wagg_kernel<<<(COUT * CIN / 4) / 256, 256>>>(weight);   // also resets g_tile_ctr

    if (fast) {
        int nsm = 148;
        cudaDeviceGetAttribute(&nsm, cudaDevAttrMultiProcessorCount, 0);
        int grid = 2 * nsm;
        if (grid > NTILES) grid = NTILES;
        cudaFuncSetAttribute(gemm_tf32_kernel, cudaFuncAttributeMaxDynamicSharedMemorySize, SMEM_TOTAL);
        gemm_tf32_kernel<<<grid, NTHREADS, SMEM_TOTAL>>>(
            tmx, tmw, (const float*)p_bb, out, 1);
    } else {
        gemm_fallback_kernel<<<dim3(L_DIM / 64, COUT / 128, B_DIM), 256>>>(
            x, (const float*)p_bb, out, 1);
    }
}

// round 15
// speedup vs baseline: 1.0526x; 1.0526x over previous
#include <cuda_runtime.h>
#include <cuda.h>
#include <cstdint>
#include <math.h>

// ============================ problem constants ============================
#define L_DIM  1024
#define B_DIM  8
#define CIN    1024
#define COUT   1024
#define KEXP   4
#define CCOND  256
#define HIDD   64

// ============================ GEMM tiling (R10 config: best measured) ============================
#define TM   128
#define TN   128
#define KC   32             // 128B row = SW128 atom
#define NKC  (CIN / KC)
#define NS   3
#define NWARP_C 8           // 8 compute warps (4Mx2N, 32x64 each) + producer
#define NTHREADS (NWARP_C * 32 + 32)   // 288

#define A_STAGE_BYTES (TM * KC * 4)
#define B_STAGE_BYTES (TN * KC * 4)
#define STAGE_BYTES   (A_STAGE_BYTES + B_STAGE_BYTES)

#define OFF_FULL   0u
#define OFF_EMPTY  (8u * NS)
#define OFF_A      1024u
#define OFF_B      (1024u + NS * A_STAGE_BYTES)
#define SMEM_TOTAL ((int)(OFF_B + NS * B_STAGE_BYTES))   // 99328 -> 2 CTAs/SM

// ============================ scratch ============================
__device__ __align__(256) float g_w[(size_t)B_DIM * COUT * CIN];
__device__ __align__(16)  float g_bb[B_DIM * COUT];
__device__ __align__(16)  float g_att[B_DIM * KEXP];
__device__ __align__(16)  float g_h[B_DIM * HIDD];

// ============================ PTX helpers (sm_100 BASELINE only) ============================
__device__ __forceinline__ uint32_t smem_u32(const void* p) {
    uint32_t a;
    asm("{ .reg .u64 t; cvta.to.shared.u64 t, %1; cvt.u32.u64 %0, t; }" : "=r"(a) : "l"(p));
    return a;
}

// PDL: wait for predecessor grid (no-op when not launched with PDL attribute)
#define GRIDDEP_WAIT() asm volatile("griddepcontrol.wait;" ::: "memory")

#define MBARRIER_INIT(addr, cnt) \
    asm volatile("mbarrier.init.shared.b64 [%0], %1;" :: "r"(addr), "r"((uint32_t)(cnt)) : "memory")

#define MBARRIER_EXPECT_TX(addr, bytes) \
    asm volatile("mbarrier.arrive.expect_tx.shared.b64 _, [%0], %1;" :: "r"(addr), "r"((uint32_t)(bytes)) : "memory")

#define MBARRIER_ARRIVE(addr) \
    asm volatile("mbarrier.arrive.shared.b64 _, [%0];" :: "r"(addr) : "memory")

#define MBAR_INVAL(addr) \
    asm volatile("mbarrier.inval.shared.b64 [%0];" :: "r"(addr) : "memory")

#define MBARRIER_WAIT_PARITY(mbar_smem_addr, phase_parity) do {                          \
    uint32_t _mbar = (uint32_t)(mbar_smem_addr);                                         \
    uint32_t _parity = (uint32_t)(phase_parity);                                         \
    uint32_t _done;                                                                      \
    asm volatile(                                                                        \
        "{\n\t"                                                                          \
        ".reg .pred p;\n\t"                                                              \
        "mbarrier.try_wait.parity.acquire.cta.shared::cta.b64 p, [%1], %2;\n\t"          \
        "selp.b32 %0, 1, 0, p;\n\t"                                                      \
        "}"                                                                              \
        : "=r"(_done) : "r"(_mbar), "r"(_parity) : "memory");                            \
    if (!_done) {                                                                        \
        asm volatile(                                                                    \
            "{\n\t"                                                                      \
            ".reg .pred P1;\n\t"                                                         \
            "WAIT_LOOP_%=:\n\t"                                                          \
            "mbarrier.try_wait.parity.acquire.cta.shared::cta.b64 P1, [%0], %1, 0x989680;\n\t" \
            "@P1 bra.uni WAIT_DONE_%=;\n\t"                                              \
            "bra.uni WAIT_LOOP_%=;\n\t"                                                  \
            "WAIT_DONE_%=:\n\t"                                                          \
            "}"                                                                          \
            :: "r"(_mbar), "r"(_parity) : "memory");                                     \
    }                                                                                    \
} while (0)

#define TMA_LOAD_3D(smem_addr, tensor_map, cx, cy, cz, mbar) \
    asm volatile( \
        "cp.async.bulk.tensor.3d.shared::cta.global.tile.mbarrier::complete_tx::bytes " \
        "[%0], [%1, {%2, %3, %4}], [%5];" \
        :: "r"((uint32_t)(smem_addr)), "l"(tensor_map), \
           "r"((int32_t)(cx)), "r"((int32_t)(cy)), "r"((int32_t)(cz)), \
           "r"((uint32_t)(mbar)) \
        : "memory")

#define FENCE_PROXY() \
    asm volatile("fence.proxy.async.shared::cta;" ::: "memory")

#define LDSM_X4(r, addr) \
    asm volatile("ldmatrix.sync.aligned.m8n8.x4.shared.b16 {%0,%1,%2,%3}, [%4];" \
        : "=r"((r)[0]), "=r"((r)[1]), "=r"((r)[2]), "=r"((r)[3]) : "r"(addr))

// tf32 round-to-nearest (ties away): add half-ulp at bit 13, mask.
__device__ __forceinline__ uint32_t tf32_rna_u32(uint32_t u) {
    return (u + 0x1000u) & 0xFFFFE000u;
}
__device__ __forceinline__ float tf32_round(float v) {
    return __uint_as_float(tf32_rna_u32(__float_as_uint(v)));
}

// mma.sync m16n8k8 tf32 (sm_80+ baseline)
__device__ __forceinline__ void mma_tf32(float* d, const uint32_t* a, const uint32_t* b) {
    asm volatile(
        "mma.sync.aligned.m16n8k8.row.col.f32.tf32.tf32.f32 "
        "{%0,%1,%2,%3}, {%4,%5,%6,%7}, {%8,%9}, {%0,%1,%2,%3};"
        : "+f"(d[0]), "+f"(d[1]), "+f"(d[2]), "+f"(d[3])
        : "r"(a[0]), "r"(a[1]), "r"(a[2]), "r"(a[3]), "r"(b[0]), "r"(b[1]));
}

// ============================ kernel 1a: fc1 hidden ============================
__global__ void attn_h_kernel(const float* __restrict__ cond,
                              const float* __restrict__ fc1w,
                              const float* __restrict__ fc1b) {
    const int w = threadIdx.x >> 5, l = threadIdx.x & 31;
    #pragma unroll
    for (int r = 0; r < 4; r++) {
        const int idx = blockIdx.x * 32 + w * 4 + r;
        const int b = idx >> 6, j = idx & 63;
        const float* c = cond + b * CCOND;
        const float* fw = fc1w + j * CCOND;
        float s = 0.0f;
        #pragma unroll
        for (int i = 0; i < CCOND / 32; i++)
            s = fmaf(c[l + 32 * i], fw[l + 32 * i], s);
        #pragma unroll
        for (int o = 16; o; o >>= 1) s += __shfl_xor_sync(0xFFFFFFFFu, s, o);
        if (l == 0) g_h[idx] = fmaxf(s + fc1b[j], 0.0f);
    }
}

// ============================ kernel 1b: logits + softmax + aggregated bias (PDL) ============================
__global__ void attn_rest_kernel(const float* __restrict__ fc2w, const float* __restrict__ fc2b,
                                 const float* __restrict__ bias) {
    __shared__ float h[B_DIM * HIDD];
    __shared__ float lo[B_DIM][KEXP];
    __shared__ float att[B_DIM][KEXP];
    const int t = threadIdx.x;   // 512 threads

    GRIDDEP_WAIT();              // attn_h results ready

    if (t < B_DIM * HIDD) h[t] = g_h[t];
    __syncthreads();

    if (t < B_DIM * KEXP) {
        const int b = t >> 2, k = t & 3;
        const float* wv = fc2w + k * HIDD;
        float acc = fc2b[k];
        #pragma unroll 8
        for (int i = 0; i < HIDD; i++) acc = fmaf(h[b * HIDD + i], wv[i], acc);
        lo[b][k] = acc * (1.0f / 30.0f);
    }
    __syncthreads();

    if (t < B_DIM) {
        float m = fmaxf(fmaxf(lo[t][0], lo[t][1]), fmaxf(lo[t][2], lo[t][3]));
        float e[KEXP], s = 0.0f;
        #pragma unroll
        for (int k = 0; k < KEXP; k++) { e[k] = expf(lo[t][k] - m); s += e[k]; }
        float inv = 1.0f / s;
        #pragma unroll
        for (int k = 0; k < KEXP; k++) { att[t][k] = e[k] * inv; g_att[t * KEXP + k] = e[k] * inv; }
    }
    __syncthreads();

    for (int idx = t; idx < B_DIM * COUT; idx += 512) {
        const int b = idx >> 10, o = idx & 1023;
        float acc = 0.0f;
        #pragma unroll
        for (int k = 0; k < KEXP; k++) acc = fmaf(att[b][k], bias[k * COUT + o], acc);
        g_bb[idx] = acc;
    }
}

// ============================ kernel 2: weight aggregation (PDL: preload overlaps attn_rest) ============================
__global__ void wagg_kernel(const float* __restrict__ weight) {
    const int t = blockIdx.x * blockDim.x + threadIdx.x;
    const float4* w4 = reinterpret_cast<const float4*>(weight);

    // Big independent loads first: overlap with attn_rest under PDL.
    float4 wk[KEXP];
    #pragma unroll
    for (int k = 0; k < KEXP; k++) wk[k] = w4[k * (COUT * CIN / 4) + t];

    GRIDDEP_WAIT();              // g_att ready (attn_rest completed)

    __shared__ float a[B_DIM * KEXP];
    if (threadIdx.x < B_DIM * KEXP) a[threadIdx.x] = g_att[threadIdx.x];
    __syncthreads();

    float4* g4 = reinterpret_cast<float4*>(g_w);
    #pragma unroll
    for (int b = 0; b < B_DIM; b++) {
        float4 acc = make_float4(0.f, 0.f, 0.f, 0.f);
        #pragma unroll
        for (int k = 0; k < KEXP; k++) {
            const float ab = a[b * KEXP + k];
            acc.x = fmaf(ab, wk[k].x, acc.x);
            acc.y = fmaf(ab, wk[k].y, acc.y);
            acc.z = fmaf(ab, wk[k].z, acc.z);
            acc.w = fmaf(ab, wk[k].w, acc.w);
        }
        acc.x = tf32_round(acc.x); acc.y = tf32_round(acc.y);
        acc.z = tf32_round(acc.z); acc.w = tf32_round(acc.w);
        g4[b * (COUT * CIN / 4) + t] = acc;
    }
}

// ============================ kernel 3: tf32 mma.sync GEMM (R10 config + PDL) ============================
__global__ void __launch_bounds__(NTHREADS, 2)
gemm_tf32_kernel(const __grid_constant__ CUtensorMap tmx,
                 const __grid_constant__ CUtensorMap tmw,
                 const float* __restrict__ bb,
                 float* __restrict__ out,
                 int enabled) {
    if (!enabled) { GRIDDEP_WAIT(); return; }
    extern __shared__ char smem[];
    const uint32_t sb = smem_u32(smem);
    const int tid  = threadIdx.x;
    const int wid  = tid >> 5;
    const int lane = tid & 31;
    const int g = lane >> 2;
    const int t = lane & 3;
    const int l0 = blockIdx.x * TM;
    const int o0 = blockIdx.y * TN;
    const int b  = blockIdx.z;

    if (tid == 0) {
        #pragma unroll
        for (int s = 0; s < NS; s++) {
            MBARRIER_INIT(sb + OFF_FULL + 8 * s, 1);
            MBARRIER_INIT(sb + OFF_EMPTY + 8 * s, NWARP_C);
        }
        FENCE_PROXY();
    }
    __syncthreads();

    GRIDDEP_WAIT();              // g_w / g_bb ready (wagg completed); init overlapped its tail

    if (wid == NWARP_C) {
        if (lane == 0) {
            int ps = 0, pp = 1;
            #pragma unroll 1
            for (int kc = 0; kc < NKC; kc++) {
                MBARRIER_WAIT_PARITY(sb + OFF_EMPTY + 8 * ps, pp);
                MBARRIER_EXPECT_TX(sb + OFF_FULL + 8 * ps, STAGE_BYTES);
                TMA_LOAD_3D(sb + OFF_A + ps * A_STAGE_BYTES, &tmx, kc * KC, b, l0, sb + OFF_FULL + 8 * ps);
                TMA_LOAD_3D(sb + OFF_B + ps * B_STAGE_BYTES, &tmw, kc * KC, o0, b, sb + OFF_FULL + 8 * ps);
                if (++ps == NS) { ps = 0; pp ^= 1; }
            }
        }
    } else {
        const int wm = wid & 3;        // 0..3 -> M offset (32 rows)
        const int wn = wid >> 2;       // 0..1 -> N offset (64 cols)
        const int srot = wid & 3;

        const int r8   = lane & 7;
        const int subA = (lane >> 3) & 1;
        const int hA   = lane >> 4;
        const int tadd = lane >> 4;
        const int hB   = (lane >> 3) & 1;
        const uint32_t uxor = (uint32_t)(r8 >> 1);
        const uint32_t vA = (uint32_t)((hA ^ (r8 & 1)) << 4);
        const uint32_t vB = (uint32_t)((hB ^ (r8 & 1)) << 4);

        uint32_t rowA[2], rowB[4];
        #pragma unroll
        for (int i = 0; i < 2; i++)
            rowA[i] = (uint32_t)(wm * 32 + i * 16 + subA * 8 + r8) * 128u;
        #pragma unroll
        for (int p = 0; p < 4; p++)
            rowB[p] = (uint32_t)(wn * 64 + (p * 2 + tadd) * 8 + r8) * 128u;

        float acc[2][8][4];
        #pragma unroll
        for (int i = 0; i < 2; i++)
            #pragma unroll
            for (int j = 0; j < 8; j++)
                #pragma unroll
                for (int q = 0; q < 4; q++) acc[i][j][q] = 0.0f;

        int cs = 0, cp = 0;
        #pragma unroll 1
        for (int kc = 0; kc < NKC; kc++) {
            MBARRIER_WAIT_PARITY(sb + OFF_FULL + 8 * cs, cp);
            const uint32_t sA = sb + OFF_A + cs * A_STAGE_BYTES;
            const uint32_t sB = sb + OFF_B + cs * B_STAGE_BYTES;

            #pragma unroll
            for (int si = 0; si < 4; si++) {
                const int s = (si + srot) & 3;
                const uint32_t offA = ((((uint32_t)s ^ uxor) & 3u) << 5) | vA;
                const uint32_t offB = ((((uint32_t)s ^ uxor) & 3u) << 5) | vB;

                uint32_t a[2][4];
                uint32_t bfr[4][4];
                LDSM_X4(a[0], sA + rowA[0] + offA);
                LDSM_X4(a[1], sA + rowA[1] + offA);
                LDSM_X4(bfr[0], sB + rowB[0] + offB);
                LDSM_X4(bfr[1], sB + rowB[1] + offB);
                LDSM_X4(bfr[2], sB + rowB[2] + offB);
                LDSM_X4(bfr[3], sB + rowB[3] + offB);

                #pragma unroll
                for (int i = 0; i < 2; i++)
                    #pragma unroll
                    for (int q = 0; q < 4; q++) a[i][q] = tf32_rna_u32(a[i][q]);

                #pragma unroll
                for (int p = 0; p < 4; p++) {
                    mma_tf32(acc[0][2 * p],     a[0], bfr[p]);
                    mma_tf32(acc[0][2 * p + 1], a[0], bfr[p] + 2);
                    mma_tf32(acc[1][2 * p],     a[1], bfr[p]);
                    mma_tf32(acc[1][2 * p + 1], a[1], bfr[p] + 2);
                }
            }

            if (lane == 0) MBARRIER_ARRIVE(sb + OFF_EMPTY + 8 * cs);
            if (++cs == NS) { cs = 0; cp ^= 1; }
        }

        const int colbase = o0 + wn * 64 + 2 * t;
        float2 bv[8];
        #pragma unroll
        for (int j = 0; j < 8; j++)
            bv[j] = *reinterpret_cast<const float2*>(bb + b * COUT + colbase + j * 8);

        #pragma unroll
        for (int i = 0; i < 2; i++) {
            #pragma unroll
            for (int p = 0; p < 2; p++) {
                const int l = l0 + wm * 32 + i * 16 + g + 8 * p;
                float* orow = out + ((size_t)l * B_DIM + b) * COUT + colbase;
                #pragma unroll
                for (int j = 0; j < 8; j++) {
                    float2 v;
                    v.x = acc[i][j][2 * p]     + bv[j].x;
                    v.y = acc[i][j][2 * p + 1] + bv[j].y;
                    *reinterpret_cast<float2*>(orow + j * 8) = v;
                }
            }
        }
    }

    __syncthreads();
    if (tid == 0) {
        #pragma unroll
        for (int s = 0; s < NS; s++) {
            MBAR_INVAL(sb + OFF_FULL + 8 * s);
            MBAR_INVAL(sb + OFF_EMPTY + 8 * s);
        }
    }
}

// ============================ fallback: SIMT fp32 GEMM ============================
__global__ void __launch_bounds__(256, 2)
gemm_fallback_kernel(const float* __restrict__ x, const float* __restrict__ bb,
                     float* __restrict__ out, int enabled) {
    if (!enabled) return;
    __shared__ float sx[64][33];
    const int l0 = blockIdx.x * 64;
    const int o0 = blockIdx.y * 128;
    const int b  = blockIdx.z;
    const int tid = threadIdx.x;
    const int tr = tid >> 5;
    const int tc = tid & 31;

    float acc[8][4];
    #pragma unroll
    for (int i = 0; i < 8; i++)
        #pragma unroll
        for (int j = 0; j < 4; j++) acc[i][j] = 0.0f;

    for (int k0 = 0; k0 < CIN; k0 += 32) {
        __syncthreads();
        #pragma unroll
        for (int i = 0; i < 8; i++) {
            const int row = tr + i * 8;
            sx[row][tc] = x[((size_t)(l0 + row) * B_DIM + b) * CIN + k0 + tc];
        }
        __syncthreads();
        #pragma unroll 4
        for (int kk = 0; kk < 32; kk++) {
            float wv[4];
            #pragma unroll
            for (int j = 0; j < 4; j++)
                wv[j] = g_w[((size_t)b * COUT + o0 + tc + 32 * j) * CIN + k0 + kk];
            #pragma unroll
            for (int i = 0; i < 8; i++) {
                const float xv = sx[tr + i * 8][kk];
                #pragma unroll
                for (int j = 0; j < 4; j++) acc[i][j] = fmaf(xv, wv[j], acc[i][j]);
            }
        }
    }
    #pragma unroll
    for (int i = 0; i < 8; i++) {
        const int l = l0 + tr + i * 8;
        #pragma unroll
        for (int j = 0; j < 4; j++) {
            const int o = o0 + tc + 32 * j;
            out[((size_t)l * B_DIM + b) * COUT + o] = acc[i][j] + bb[b * COUT + o];
        }
    }
}

// ============================ host launch ============================
typedef CUresult (CUDAAPI *EncodeTiledFn)(
    CUtensorMap*, CUtensorMapDataType, cuuint32_t, void*,
    const cuuint64_t*, const cuuint64_t*, const cuuint32_t*, const cuuint32_t*,
    CUtensorMapInterleave, CUtensorMapSwizzle, CUtensorMapL2promotion, CUtensorMapFloatOOBfill);

extern "C" void kernel_launch(void* const* d_in, const int* in_sizes, int n_in,
                              void* d_out, int out_size) {
    const float* x      = (const float*)d_in[0];
    const float* cond   = (const float*)d_in[1];
    const float* fc1w   = (const float*)d_in[2];
    const float* fc1b   = (const float*)d_in[3];
    const float* fc2w   = (const float*)d_in[4];
    const float* fc2b   = (const float*)d_in[5];
    const float* weight = (const float*)d_in[6];
    const float* bias   = (const float*)d_in[7];
    float* out = (float*)d_out;

    void *p_w = nullptr, *p_bb = nullptr;
    cudaGetSymbolAddress(&p_w, g_w);
    cudaGetSymbolAddress(&p_bb, g_bb);

    EncodeTiledFn enc = nullptr;
    {
        cudaDriverEntryPointQueryResult qres = cudaDriverEntryPointSymbolNotFound;
        cudaError_t e = cudaGetDriverEntryPointByVersion(
            "cuTensorMapEncodeTiled", (void**)&enc, 12000, cudaEnableDefault, &qres);
        if (e != cudaSuccess || qres != cudaDriverEntryPointSuccess) enc = nullptr;
        if (!enc) {
            qres = cudaDriverEntryPointSymbolNotFound;
            e = cudaGetDriverEntryPoint("cuTensorMapEncodeTiled", (void**)&enc,
                                        cudaEnableDefault, &qres);
            if (e != cudaSuccess || qres != cudaDriverEntryPointSuccess) enc = nullptr;
        }
    }

    CUtensorMap tmx, tmw;
    bool fast = (enc != nullptr);
    if (fast) {
        cuuint64_t dimsx[3]    = {CIN, B_DIM, L_DIM};
        cuuint64_t stridesx[2] = {(cuuint64_t)CIN * 4, (cuuint64_t)CIN * B_DIM * 4};
        cuuint32_t boxx[3]     = {KC, 1, TM};
        cuuint32_t es[3]       = {1, 1, 1};
        if (enc(&tmx, CU_TENSOR_MAP_DATA_TYPE_FLOAT32, 3, (void*)x, dimsx, stridesx, boxx, es,
                CU_TENSOR_MAP_INTERLEAVE_NONE, CU_TENSOR_MAP_SWIZZLE_128B,
                CU_TENSOR_MAP_L2_PROMOTION_L2_128B, CU_TENSOR_MAP_FLOAT_OOB_FILL_NONE)
            != CUDA_SUCCESS) fast = false;
        cuuint64_t dimsw[3]    = {CIN, COUT, B_DIM};
        cuuint64_t stridesw[2] = {(cuuint64_t)CIN * 4, (cuuint64_t)CIN * COUT * 4};
        cuuint32_t boxw[3]     = {KC, TN, 1};
        if (fast &&
            enc(&tmw, CU_TENSOR_MAP_DATA_TYPE_FLOAT32, 3, p_w, dimsw, stridesw, boxw, es,
                CU_TENSOR_MAP_INTERLEAVE_NONE, CU_TENSOR_MAP_SWIZZLE_128B,
                CU_TENSOR_MAP_L2_PROMOTION_L2_128B, CU_TENSOR_MAP_FLOAT_OOB_FILL_NONE)
            != CUDA_SUCCESS) fast = false;
    }
    if (!fast) {
        memset(&tmx, 0, sizeof(tmx));
        memset(&tmw, 0, sizeof(tmw));
    }

    // attn_h: normal launch (serializes with previous graph replay's gemm; avoids
    // cross-replay overlap hazard on g_bb/g_w).
    attn_h_kernel<<<16, 256>>>(cond, fc1w, fc1b);

    // PDL launch attribute for the dependent chain.
    cudaLaunchAttribute pdl[1];
    pdl[0].id = cudaLaunchAttributeProgrammaticStreamSerialization;
    pdl[0].val.programmaticStreamSerializationAllowed = 1;

    {
        cudaLaunchConfig_t cfg = {};
        cfg.gridDim = dim3(1, 1, 1);
        cfg.blockDim = dim3(512, 1, 1);
        cfg.attrs = pdl; cfg.numAttrs = 1;
        cudaLaunchKernelEx(&cfg, attn_rest_kernel, fc2w, fc2b, bias);
    }
    {
        cudaLaunchConfig_t cfg = {};
        cfg.gridDim = dim3((COUT * CIN / 4) / 256, 1, 1);
        cfg.blockDim = dim3(256, 1, 1);
        cfg.attrs = pdl; cfg.numAttrs = 1;
        cudaLaunchKernelEx(&cfg, wagg_kernel, weight);
    }

    if (fast) {
        cudaFuncSetAttribute(gemm_tf32_kernel, cudaFuncAttributeMaxDynamicSharedMemorySize, SMEM_TOTAL);
        cudaLaunchConfig_t cfg = {};
        cfg.gridDim = dim3(L_DIM / TM, COUT / TN, B_DIM);
        cfg.blockDim = dim3(NTHREADS, 1, 1);
        cfg.dynamicSmemBytes = SMEM_TOTAL;
        cfg.attrs = pdl; cfg.numAttrs = 1;
        int en = 1;
        cudaLaunchKernelEx(&cfg, gemm_tf32_kernel, tmx, tmw, (const float*)p_bb, out, en);
    } else {
        gemm_fallback_kernel<<<dim3(L_DIM / 64, COUT / 128, B_DIM), 256>>>(
            x, (const float*)p_bb, out, 1);
    }
}

// round 17
// speedup vs baseline: 1.0723x; 1.0187x over previous
#include <cuda_runtime.h>
#include <cuda.h>
#include <cstdint>
#include <math.h>

// ============================ problem constants ============================
#define L_DIM  1024
#define B_DIM  8
#define CIN    1024
#define COUT   1024
#define KEXP   4
#define CCOND  256
#define HIDD   64

// ============================ GEMM tiling (R10 config: best measured) ============================
#define TM   128
#define TN   128
#define KC   32             // 128B row = SW128 atom
#define NKC  (CIN / KC)
#define NS   3
#define NWARP_C 8           // 8 compute warps (4Mx2N, 32x64 each) + producer
#define NTHREADS (NWARP_C * 32 + 32)   // 288

#define A_STAGE_BYTES (TM * KC * 4)
#define B_STAGE_BYTES (TN * KC * 4)

#define OFF_FULL   0u
#define OFF_EMPTY  (8u * NS)
#define OFF_A      1024u
#define OFF_B      (1024u + NS * A_STAGE_BYTES)
#define SMEM_TOTAL ((int)(OFF_B + NS * B_STAGE_BYTES))   // 99328 -> 2 CTAs/SM

// ============================ scratch ============================
__device__ __align__(256) float g_w[(size_t)B_DIM * COUT * CIN];
__device__ __align__(16)  float g_bb[B_DIM * COUT];
__device__ __align__(16)  float g_h[B_DIM * HIDD];

// ============================ PTX helpers (sm_100 BASELINE only) ============================
__device__ __forceinline__ uint32_t smem_u32(const void* p) {
    uint32_t a;
    asm("{ .reg .u64 t; cvta.to.shared.u64 t, %1; cvt.u32.u64 %0, t; }" : "=r"(a) : "l"(p));
    return a;
}

// PDL: wait for predecessor grid (no-op when not launched with PDL attribute)
#define GRIDDEP_WAIT() asm volatile("griddepcontrol.wait;" ::: "memory")

#define MBARRIER_INIT(addr, cnt) \
    asm volatile("mbarrier.init.shared.b64 [%0], %1;" :: "r"(addr), "r"((uint32_t)(cnt)) : "memory")

#define MBARRIER_EXPECT_TX(addr, bytes) \
    asm volatile("mbarrier.arrive.expect_tx.shared.b64 _, [%0], %1;" :: "r"(addr), "r"((uint32_t)(bytes)) : "memory")

#define MBARRIER_ARRIVE(addr) \
    asm volatile("mbarrier.arrive.shared.b64 _, [%0];" :: "r"(addr) : "memory")

#define MBAR_INVAL(addr) \
    asm volatile("mbarrier.inval.shared.b64 [%0];" :: "r"(addr) : "memory")

#define MBARRIER_WAIT_PARITY(mbar_smem_addr, phase_parity) do {                          \
    uint32_t _mbar = (uint32_t)(mbar_smem_addr);                                         \
    uint32_t _parity = (uint32_t)(phase_parity);                                         \
    uint32_t _done;                                                                      \
    asm volatile(                                                                        \
        "{\n\t"                                                                          \
        ".reg .pred p;\n\t"                                                              \
        "mbarrier.try_wait.parity.acquire.cta.shared::cta.b64 p, [%1], %2;\n\t"          \
        "selp.b32 %0, 1, 0, p;\n\t"                                                      \
        "}"                                                                              \
        : "=r"(_done) : "r"(_mbar), "r"(_parity) : "memory");                            \
    if (!_done) {                                                                        \
        asm volatile(                                                                    \
            "{\n\t"                                                                      \
            ".reg .pred P1;\n\t"                                                         \
            "WAIT_LOOP_%=:\n\t"                                                          \
            "mbarrier.try_wait.parity.acquire.cta.shared::cta.b64 P1, [%0], %1, 0x989680;\n\t" \
            "@P1 bra.uni WAIT_DONE_%=;\n\t"                                              \
            "bra.uni WAIT_LOOP_%=;\n\t"                                                  \
            "WAIT_DONE_%=:\n\t"                                                          \
            "}"                                                                          \
            :: "r"(_mbar), "r"(_parity) : "memory");                                     \
    }                                                                                    \
} while (0)

#define TMA_LOAD_3D(smem_addr, tensor_map, cx, cy, cz, mbar) \
    asm volatile( \
        "cp.async.bulk.tensor.3d.shared::cta.global.tile.mbarrier::complete_tx::bytes " \
        "[%0], [%1, {%2, %3, %4}], [%5];" \
        :: "r"((uint32_t)(smem_addr)), "l"(tensor_map), \
           "r"((int32_t)(cx)), "r"((int32_t)(cy)), "r"((int32_t)(cz)), \
           "r"((uint32_t)(mbar)) \
        : "memory")

#define FENCE_PROXY() \
    asm volatile("fence.proxy.async.shared::cta;" ::: "memory")

#define LDSM_X4(r, addr) \
    asm volatile("ldmatrix.sync.aligned.m8n8.x4.shared.b16 {%0,%1,%2,%3}, [%4];" \
        : "=r"((r)[0]), "=r"((r)[1]), "=r"((r)[2]), "=r"((r)[3]) : "r"(addr))

// tf32 round-to-nearest (ties away): add half-ulp at bit 13, mask.
__device__ __forceinline__ uint32_t tf32_rna_u32(uint32_t u) {
    return (u + 0x1000u) & 0xFFFFE000u;
}
__device__ __forceinline__ float tf32_round(float v) {
    return __uint_as_float(tf32_rna_u32(__float_as_uint(v)));
}

// mma.sync m16n8k8 tf32 (sm_80+ baseline)
__device__ __forceinline__ void mma_tf32(float* d, const uint32_t* a, const uint32_t* b) {
    asm volatile(
        "mma.sync.aligned.m16n8k8.row.col.f32.tf32.tf32.f32 "
        "{%0,%1,%2,%3}, {%4,%5,%6,%7}, {%8,%9}, {%0,%1,%2,%3};"
        : "+f"(d[0]), "+f"(d[1]), "+f"(d[2]), "+f"(d[3])
        : "r"(a[0]), "r"(a[1]), "r"(a[2]), "r"(a[3]), "r"(b[0]), "r"(b[1]));
}

// ============================ kernel 1: fc1 hidden ============================
__global__ void attn_h_kernel(const float* __restrict__ cond,
                              const float* __restrict__ fc1w,
                              const float* __restrict__ fc1b) {
    const int w = threadIdx.x >> 5, l = threadIdx.x & 31;
    #pragma unroll
    for (int r = 0; r < 4; r++) {
        const int idx = blockIdx.x * 32 + w * 4 + r;
        const int b = idx >> 6, j = idx & 63;
        const float* c = cond + b * CCOND;
        const float* fw = fc1w + j * CCOND;
        float s = 0.0f;
        #pragma unroll
        for (int i = 0; i < CCOND / 32; i++)
            s = fmaf(c[l + 32 * i], fw[l + 32 * i], s);
        #pragma unroll
        for (int o = 16; o; o >>= 1) s += __shfl_xor_sync(0xFFFFFFFFu, s, o);
        if (l == 0) g_h[idx] = fmaxf(s + fc1b[j], 0.0f);
    }
}

// ============================ kernel 2: wagg (+ local softmax, + g_bb) ============================
// Each block recomputes logits+softmax from g_h (cheap, L2-resident); blocks 0-31 also write g_bb.
__global__ void wagg_kernel(const float* __restrict__ weight,
                            const float* __restrict__ fc2w, const float* __restrict__ fc2b,
                            const float* __restrict__ bias) {
    const int t = blockIdx.x * blockDim.x + threadIdx.x;
    const float4* w4 = reinterpret_cast<const float4*>(weight);

    // Big independent loads first: overlap with attn_h under PDL.
    float4 wk[KEXP];
    #pragma unroll
    for (int k = 0; k < KEXP; k++) wk[k] = w4[k * (COUT * CIN / 4) + t];

    GRIDDEP_WAIT();              // g_h ready (attn_h completed)

    __shared__ float lo[B_DIM * KEXP];
    __shared__ float att[B_DIM][KEXP];
    if (threadIdx.x < B_DIM * KEXP) {
        const int b = threadIdx.x >> 2, k = threadIdx.x & 3;
        const float* hv = g_h + b * HIDD;
        const float* wv = fc2w + k * HIDD;
        float acc = fc2b[k];
        #pragma unroll 8
        for (int i = 0; i < HIDD; i++) acc = fmaf(hv[i], wv[i], acc);
        lo[threadIdx.x] = acc * (1.0f / 30.0f);
    }
    __syncthreads();
    if (threadIdx.x < B_DIM) {
        const int b = threadIdx.x;
        float m = fmaxf(fmaxf(lo[b * 4], lo[b * 4 + 1]), fmaxf(lo[b * 4 + 2], lo[b * 4 + 3]));
        float e[KEXP], s = 0.0f;
        #pragma unroll
        for (int k = 0; k < KEXP; k++) { e[k] = expf(lo[b * 4 + k] - m); s += e[k]; }
        float inv = 1.0f / s;
        #pragma unroll
        for (int k = 0; k < KEXP; k++) att[b][k] = e[k] * inv;
    }
    __syncthreads();

    float4* g4 = reinterpret_cast<float4*>(g_w);
    #pragma unroll
    for (int b = 0; b < B_DIM; b++) {
        float4 acc = make_float4(0.f, 0.f, 0.f, 0.f);
        #pragma unroll
        for (int k = 0; k < KEXP; k++) {
            const float ab = att[b][k];
            acc.x = fmaf(ab, wk[k].x, acc.x);
            acc.y = fmaf(ab, wk[k].y, acc.y);
            acc.z = fmaf(ab, wk[k].z, acc.z);
            acc.w = fmaf(ab, wk[k].w, acc.w);
        }
        acc.x = tf32_round(acc.x); acc.y = tf32_round(acc.y);
        acc.z = tf32_round(acc.z); acc.w = tf32_round(acc.w);
        g4[b * (COUT * CIN / 4) + t] = acc;
    }

    // aggregated bias: blocks 0..31 cover all 8192 entries
    if (blockIdx.x < 32) {
        const int idx = blockIdx.x * 256 + threadIdx.x;
        const int b = idx >> 10, o = idx & 1023;
        float acc = 0.0f;
        #pragma unroll
        for (int k = 0; k < KEXP; k++) acc = fmaf(att[b][k], bias[k * COUT + o], acc);
        g_bb[idx] = acc;
    }
}

// ============================ kernel 3: tf32 mma.sync GEMM (A-prefetch pre-wait) ============================
// full barriers: 2 arrive.expect_tx per pass (A then B) -> init count 2.
__global__ void __launch_bounds__(NTHREADS, 2)
gemm_tf32_kernel(const __grid_constant__ CUtensorMap tmx,
                 const __grid_constant__ CUtensorMap tmw,
                 const float* __restrict__ bb,
                 float* __restrict__ out,
                 int enabled) {
    if (!enabled) { GRIDDEP_WAIT(); return; }
    extern __shared__ char smem[];
    const uint32_t sb = smem_u32(smem);
    const int tid  = threadIdx.x;
    const int wid  = tid >> 5;
    const int lane = tid & 31;
    const int g = lane >> 2;
    const int t = lane & 3;
    const int l0 = blockIdx.x * TM;
    const int o0 = blockIdx.y * TN;
    const int b  = blockIdx.z;

    if (tid == 0) {
        #pragma unroll
        for (int s = 0; s < NS; s++) {
            MBARRIER_INIT(sb + OFF_FULL + 8 * s, 2);        // A + B arrive.expect_tx per pass
            MBARRIER_INIT(sb + OFF_EMPTY + 8 * s, NWARP_C);
        }
        FENCE_PROXY();
    }
    __syncthreads();

    // A-prefetch (x does not depend on wagg): issue before the PDL wait.
    if (wid == NWARP_C && lane == 0) {
        #pragma unroll
        for (int i = 0; i < NS; i++) {
            MBARRIER_EXPECT_TX(sb + OFF_FULL + 8 * i, A_STAGE_BYTES);
            TMA_LOAD_3D(sb + OFF_A + i * A_STAGE_BYTES, &tmx, i * KC, b, l0, sb + OFF_FULL + 8 * i);
        }
    }

    GRIDDEP_WAIT();              // g_w / g_bb ready (wagg completed)

    if (wid == NWARP_C) {
        if (lane == 0) {
            // B side of the preloaded stages
            #pragma unroll
            for (int i = 0; i < NS; i++) {
                MBARRIER_EXPECT_TX(sb + OFF_FULL + 8 * i, B_STAGE_BYTES);
                TMA_LOAD_3D(sb + OFF_B + i * B_STAGE_BYTES, &tmw, i * KC, o0, b, sb + OFF_FULL + 8 * i);
            }
            // steady state: refill stage after consumers release it.
            // empty[s] first completion has parity 0 -> pp starts 0.
            int ps = 0, pp = 0;
            #pragma unroll 1
            for (int kc = NS; kc < NKC; kc++) {
                MBARRIER_WAIT_PARITY(sb + OFF_EMPTY + 8 * ps, pp);
                MBARRIER_EXPECT_TX(sb + OFF_FULL + 8 * ps, A_STAGE_BYTES);
                TMA_LOAD_3D(sb + OFF_A + ps * A_STAGE_BYTES, &tmx, kc * KC, b, l0, sb + OFF_FULL + 8 * ps);
                MBARRIER_EXPECT_TX(sb + OFF_FULL + 8 * ps, B_STAGE_BYTES);
                TMA_LOAD_3D(sb + OFF_B + ps * B_STAGE_BYTES, &tmw, kc * KC, o0, b, sb + OFF_FULL + 8 * ps);
                if (++ps == NS) { ps = 0; pp ^= 1; }
            }
        }
    } else {
        const int wm = wid & 3;        // 0..3 -> M offset (32 rows)
        const int wn = wid >> 2;       // 0..1 -> N offset (64 cols)
        const int srot = wid & 3;

        const int r8   = lane & 7;
        const int subA = (lane >> 3) & 1;
        const int hA   = lane >> 4;
        const int tadd = lane >> 4;
        const int hB   = (lane >> 3) & 1;
        const uint32_t uxor = (uint32_t)(r8 >> 1);
        const uint32_t vA = (uint32_t)((hA ^ (r8 & 1)) << 4);
        const uint32_t vB = (uint32_t)((hB ^ (r8 & 1)) << 4);

        uint32_t rowA[2], rowB[4];
        #pragma unroll
        for (int i = 0; i < 2; i++)
            rowA[i] = (uint32_t)(wm * 32 + i * 16 + subA * 8 + r8) * 128u;
        #pragma unroll
        for (int p = 0; p < 4; p++)
            rowB[p] = (uint32_t)(wn * 64 + (p * 2 + tadd) * 8 + r8) * 128u;

        float acc[2][8][4];
        #pragma unroll
        for (int i = 0; i < 2; i++)
            #pragma unroll
            for (int j = 0; j < 8; j++)
                #pragma unroll
                for (int q = 0; q < 4; q++) acc[i][j][q] = 0.0f;

        int cs = 0, cp = 0;
        #pragma unroll 1
        for (int kc = 0; kc < NKC; kc++) {
            MBARRIER_WAIT_PARITY(sb + OFF_FULL + 8 * cs, cp);
            const uint32_t sA = sb + OFF_A + cs * A_STAGE_BYTES;
            const uint32_t sB = sb + OFF_B + cs * B_STAGE_BYTES;

            #pragma unroll
            for (int si = 0; si < 4; si++) {
                const int s = (si + srot) & 3;
                const uint32_t offA = ((((uint32_t)s ^ uxor) & 3u) << 5) | vA;
                const uint32_t offB = ((((uint32_t)s ^ uxor) & 3u) << 5) | vB;

                uint32_t a[2][4];
                uint32_t bfr[4][4];
                LDSM_X4(a[0], sA + rowA[0] + offA);
                LDSM_X4(a[1], sA + rowA[1] + offA);
                LDSM_X4(bfr[0], sB + rowB[0] + offB);
                LDSM_X4(bfr[1], sB + rowB[1] + offB);
                LDSM_X4(bfr[2], sB + rowB[2] + offB);
                LDSM_X4(bfr[3], sB + rowB[3] + offB);

                #pragma unroll
                for (int i = 0; i < 2; i++)
                    #pragma unroll
                    for (int q = 0; q < 4; q++) a[i][q] = tf32_rna_u32(a[i][q]);

                #pragma unroll
                for (int p = 0; p < 4; p++) {
                    mma_tf32(acc[0][2 * p],     a[0], bfr[p]);
                    mma_tf32(acc[0][2 * p + 1], a[0], bfr[p] + 2);
                    mma_tf32(acc[1][2 * p],     a[1], bfr[p]);
                    mma_tf32(acc[1][2 * p + 1], a[1], bfr[p] + 2);
                }
            }

            if (lane == 0) MBARRIER_ARRIVE(sb + OFF_EMPTY + 8 * cs);
            if (++cs == NS) { cs = 0; cp ^= 1; }
        }

        const int colbase = o0 + wn * 64 + 2 * t;
        float2 bv[8];
        #pragma unroll
        for (int j = 0; j < 8; j++)
            bv[j] = *reinterpret_cast<const float2*>(bb + b * COUT + colbase + j * 8);

        #pragma unroll
        for (int i = 0; i < 2; i++) {
            #pragma unroll
            for (int p = 0; p < 2; p++) {
                const int l = l0 + wm * 32 + i * 16 + g + 8 * p;
                float* orow = out + ((size_t)l * B_DIM + b) * COUT + colbase;
                #pragma unroll
                for (int j = 0; j < 8; j++) {
                    float2 v;
                    v.x = acc[i][j][2 * p]     + bv[j].x;
                    v.y = acc[i][j][2 * p + 1] + bv[j].y;
                    *reinterpret_cast<float2*>(orow + j * 8) = v;
                }
            }
        }
    }

    __syncthreads();
    if (tid == 0) {
        #pragma unroll
        for (int s = 0; s < NS; s++) {
            MBAR_INVAL(sb + OFF_FULL + 8 * s);
            MBAR_INVAL(sb + OFF_EMPTY + 8 * s);
        }
    }
}

// ============================ fallback: SIMT fp32 GEMM ============================
__global__ void __launch_bounds__(256, 2)
gemm_fallback_kernel(const float* __restrict__ x, const float* __restrict__ bb,
                     float* __restrict__ out, int enabled) {
    if (!enabled) return;
    __shared__ float sx[64][33];
    const int l0 = blockIdx.x * 64;
    const int o0 = blockIdx.y * 128;
    const int b  = blockIdx.z;
    const int tid = threadIdx.x;
    const int tr = tid >> 5;
    const int tc = tid & 31;

    float acc[8][4];
    #pragma unroll
    for (int i = 0; i < 8; i++)
        #pragma unroll
        for (int j = 0; j < 4; j++) acc[i][j] = 0.0f;

    for (int k0 = 0; k0 < CIN; k0 += 32) {
        __syncthreads();
        #pragma unroll
        for (int i = 0; i < 8; i++) {
            const int row = tr + i * 8;
            sx[row][tc] = x[((size_t)(l0 + row) * B_DIM + b) * CIN + k0 + tc];
        }
        __syncthreads();
        #pragma unroll 4
        for (int kk = 0; kk < 32; kk++) {
            float wv[4];
            #pragma unroll
            for (int j = 0; j < 4; j++)
                wv[j] = g_w[((size_t)b * COUT + o0 + tc + 32 * j) * CIN + k0 + kk];
            #pragma unroll
            for (int i = 0; i < 8; i++) {
                const float xv = sx[tr + i * 8][kk];
                #pragma unroll
                for (int j = 0; j < 4; j++) acc[i][j] = fmaf(xv, wv[j], acc[i][j]);
            }
        }
    }
    #pragma unroll
    for (int i = 0; i < 8; i++) {
        const int l = l0 + tr + i * 8;
        #pragma unroll
        for (int j = 0; j < 4; j++) {
            const int o = o0 + tc + 32 * j;
            out[((size_t)l * B_DIM + b) * COUT + o] = acc[i][j] + bb[b * COUT + o];
        }
    }
}

// ============================ host launch ============================
typedef CUresult (CUDAAPI *EncodeTiledFn)(
    CUtensorMap*, CUtensorMapDataType, cuuint32_t, void*,
    const cuuint64_t*, const cuuint64_t*, const cuuint32_t*, const cuuint32_t*,
    CUtensorMapInterleave, CUtensorMapSwizzle, CUtensorMapL2promotion, CUtensorMapFloatOOBfill);

extern "C" void kernel_launch(void* const* d_in, const int* in_sizes, int n_in,
                              void* d_out, int out_size) {
    const float* x      = (const float*)d_in[0];
    const float* cond   = (const float*)d_in[1];
    const float* fc1w   = (const float*)d_in[2];
    const float* fc1b   = (const float*)d_in[3];
    const float* fc2w   = (const float*)d_in[4];
    const float* fc2b   = (const float*)d_in[5];
    const float* weight = (const float*)d_in[6];
    const float* bias   = (const float*)d_in[7];
    float* out = (float*)d_out;

    void *p_w = nullptr, *p_bb = nullptr;
    cudaGetSymbolAddress(&p_w, g_w);
    cudaGetSymbolAddress(&p_bb, g_bb);

    EncodeTiledFn enc = nullptr;
    {
        cudaDriverEntryPointQueryResult qres = cudaDriverEntryPointSymbolNotFound;
        cudaError_t e = cudaGetDriverEntryPointByVersion(
            "cuTensorMapEncodeTiled", (void**)&enc, 12000, cudaEnableDefault, &qres);
        if (e != cudaSuccess || qres != cudaDriverEntryPointSuccess) enc = nullptr;
        if (!enc) {
            qres = cudaDriverEntryPointSymbolNotFound;
            e = cudaGetDriverEntryPoint("cuTensorMapEncodeTiled", (void**)&enc,
                                        cudaEnableDefault, &qres);
            if (e != cudaSuccess || qres != cudaDriverEntryPointSuccess) enc = nullptr;
        }
    }

    CUtensorMap tmx, tmw;
    bool fast = (enc != nullptr);
    if (fast) {
        cuuint64_t dimsx[3]    = {CIN, B_DIM, L_DIM};
        cuuint64_t stridesx[2] = {(cuuint64_t)CIN * 4, (cuuint64_t)CIN * B_DIM * 4};
        cuuint32_t boxx[3]     = {KC, 1, TM};
        cuuint32_t es[3]       = {1, 1, 1};
        if (enc(&tmx, CU_TENSOR_MAP_DATA_TYPE_FLOAT32, 3, (void*)x, dimsx, stridesx, boxx, es,
                CU_TENSOR_MAP_INTERLEAVE_NONE, CU_TENSOR_MAP_SWIZZLE_128B,
                CU_TENSOR_MAP_L2_PROMOTION_L2_128B, CU_TENSOR_MAP_FLOAT_OOB_FILL_NONE)
            != CUDA_SUCCESS) fast = false;
        cuuint64_t dimsw[3]    = {CIN, COUT, B_DIM};
        cuuint64_t stridesw[2] = {(cuuint64_t)CIN * 4, (cuuint64_t)CIN * COUT * 4};
        cuuint32_t boxw[3]     = {KC, TN, 1};
        if (fast &&
            enc(&tmw, CU_TENSOR_MAP_DATA_TYPE_FLOAT32, 3, p_w, dimsw, stridesw, boxw, es,
                CU_TENSOR_MAP_INTERLEAVE_NONE, CU_TENSOR_MAP_SWIZZLE_128B,
                CU_TENSOR_MAP_L2_PROMOTION_L2_128B, CU_TENSOR_MAP_FLOAT_OOB_FILL_NONE)
            != CUDA_SUCCESS) fast = false;
    }
    if (!fast) {
        memset(&tmx, 0, sizeof(tmx));
        memset(&tmw, 0, sizeof(tmw));
    }

    attn_h_kernel<<<16, 256>>>(cond, fc1w, fc1b);

    cudaLaunchAttribute pdl[1];
    pdl[0].id = cudaLaunchAttributeProgrammaticStreamSerialization;
    pdl[0].val.programmaticStreamSerializationAllowed = 1;

    {
        cudaLaunchConfig_t cfg = {};
        cfg.gridDim = dim3((COUT * CIN / 4) / 256, 1, 1);
        cfg.blockDim = dim3(256, 1, 1);
        cfg.attrs = pdl; cfg.numAttrs = 1;
        cudaLaunchKernelEx(&cfg, wagg_kernel, weight, fc2w, fc2b, bias);
    }

    if (fast) {
        cudaFuncSetAttribute(gemm_tf32_kernel, cudaFuncAttributeMaxDynamicSharedMemorySize, SMEM_TOTAL);
        cudaLaunchConfig_t cfg = {};
        cfg.gridDim = dim3(L_DIM / TM, COUT / TN, B_DIM);
        cfg.blockDim = dim3(NTHREADS, 1, 1);
        cfg.dynamicSmemBytes = SMEM_TOTAL;
        cfg.attrs = pdl; cfg.numAttrs = 1;
        int en = 1;
        cudaLaunchKernelEx(&cfg, gemm_tf32_kernel, tmx, tmw, (const float*)p_bb, out, en);
    } else {
        gemm_fallback_kernel<<<dim3(L_DIM / 64, COUT / 128, B_DIM), 256>>>(
            x, (const float*)p_bb, out, 1);
    }
}